// round 4
// baseline (speedup 1.0000x reference)
#include <cuda_runtime.h>
#include <cuda_bf16.h>
#include <math.h>

// Problem constants
#define BB 2
#define CC 256
#define NN 4096
#define RR 8
#define GG 4
#define CG 64   // C / G

// Scratch (static device globals: allocation-free rule)
// g_qk[p][b][r][n]:  p: 0=qL, 1=kU, 2=qU, 3=kL
// g_v[d][b][c][n]:   d=0 -> vU(fU) used by LU, d=1 -> vL(fL) used by UL
// g_invz[d][b][n]:   1 / sum_m exp(S[n,m])
__device__ float g_qk[4][BB][RR][NN];
__device__ float g_v[2][BB][CC][NN];
__device__ float g_invz[2][BB][NN];

// ---------------------------------------------------------------------------
// K1: fused rank-8 projections (qL from xL, kU from xU, qU from xU, kL from xL)
// grid (NN/256, BB), block 256: one n per thread, 32 accumulators.
// ---------------------------------------------------------------------------
__global__ __launch_bounds__(256) void k_proj(
    const float* __restrict__ fL, const float* __restrict__ fU,
    const float* __restrict__ qLw, const float* __restrict__ qLb,
    const float* __restrict__ kUw, const float* __restrict__ kUb,
    const float* __restrict__ qUw, const float* __restrict__ qUb,
    const float* __restrict__ kLw, const float* __restrict__ kLb)
{
    __shared__ float ws[4][RR * CC];     // 32 KB of weights
    int tid = threadIdx.x;
    for (int i = tid; i < RR * CC; i += 256) {
        ws[0][i] = qLw[i];
        ws[1][i] = kUw[i];
        ws[2][i] = qUw[i];
        ws[3][i] = kLw[i];
    }
    __syncthreads();

    int b = blockIdx.y;
    int n = blockIdx.x * 256 + tid;
    const float* xl = fL + (size_t)b * CC * NN + n;
    const float* xu = fU + (size_t)b * CC * NN + n;

    float a0[RR], a1[RR], a2[RR], a3[RR];
#pragma unroll
    for (int r = 0; r < RR; r++) { a0[r] = a1[r] = a2[r] = a3[r] = 0.f; }

    for (int c = 0; c < CC; c++) {
        float lx = xl[(size_t)c * NN];
        float ux = xu[(size_t)c * NN];
#pragma unroll
        for (int r = 0; r < RR; r++) {
            a0[r] = fmaf(ws[0][r * CC + c], lx, a0[r]);
            a1[r] = fmaf(ws[1][r * CC + c], ux, a1[r]);
            a2[r] = fmaf(ws[2][r * CC + c], ux, a2[r]);
            a3[r] = fmaf(ws[3][r * CC + c], lx, a3[r]);
        }
    }
#pragma unroll
    for (int r = 0; r < RR; r++) {
        g_qk[0][b][r][n] = a0[r] + qLb[r];
        g_qk[1][b][r][n] = a1[r] + kUb[r];
        g_qk[2][b][r][n] = a2[r] + qUb[r];
        g_qk[3][b][r][n] = a3[r] + kLb[r];
    }
}

// ---------------------------------------------------------------------------
// K2: grouped 1x1x1 v-conv for both directions.
// grid (NN/128, GG, 2*BB), block 128: one n per thread, 64 accumulators.
// Weights stored transposed in SMEM so the unrolled co loop reads contiguously.
// ---------------------------------------------------------------------------
__global__ __launch_bounds__(128) void k_vconv(
    const float* __restrict__ fL, const float* __restrict__ fU,
    const float* __restrict__ vUw, const float* __restrict__ vUb,
    const float* __restrict__ vLw, const float* __restrict__ vLb)
{
    int z = blockIdx.z;
    int d = z >> 1;        // 0: LU uses vU(fU);  1: UL uses vL(fL)
    int b = z & 1;
    int g = blockIdx.y;
    int tid = threadIdx.x;
    int n = blockIdx.x * 128 + tid;

    const float* x    = (d == 0) ? fU  : fL;
    const float* wsrc = (d == 0) ? vUw : vLw;
    const float* bsrc = (d == 0) ? vUb : vLb;

    __shared__ float wT[CG][CG];   // wT[ci][co] = w[g][co][ci]
    for (int i = tid; i < CG * CG; i += 128) {
        int co = i / CG, ci = i % CG;
        wT[ci][co] = wsrc[(g * CG + co) * CG + ci];
    }
    __syncthreads();

    float acc[CG];
#pragma unroll
    for (int co = 0; co < CG; co++) acc[co] = 0.f;

    const float* xp = x + ((size_t)b * CC + g * CG) * NN + n;
    for (int ci = 0; ci < CG; ci++) {
        float xv = xp[(size_t)ci * NN];
#pragma unroll
        for (int co = 0; co < CG; co++)
            acc[co] = fmaf(wT[ci][co], xv, acc[co]);
    }
#pragma unroll
    for (int co = 0; co < CG; co++)
        g_v[d][b][g * CG + co][n] = acc[co] + bsrc[g * CG + co];
}

// ---------------------------------------------------------------------------
// K3: softmax normalizers. Logits are bounded (|S| <~ 11) so no max-shift is
// needed: invZ[n] = 1 / sum_m exp(S[n,m]).
// grid (NN/16, BB, 2), block 256: 16 rows/block, 16 lanes per row.
// k tile staged through SMEM in 512-wide chunks (shared by the 16 rows).
// ---------------------------------------------------------------------------
__global__ __launch_bounds__(256) void k_softstats()
{
    int d = blockIdx.z, b = blockIdx.y;
    int tid = threadIdx.x;
    int row  = blockIdx.x * 16 + (tid >> 4);
    int lane = tid & 15;
    int qi = d ? 2 : 0;
    int ki = d ? 3 : 1;

    __shared__ float ks[RR][512];   // 16 KB

    float q[RR];
#pragma unroll
    for (int r = 0; r < RR; r++) q[r] = g_qk[qi][b][r][row];

    float sm = 0.f;
    for (int m0 = 0; m0 < NN; m0 += 512) {
        __syncthreads();
        for (int i = tid; i < RR * 512; i += 256)
            ks[i >> 9][i & 511] = g_qk[ki][b][i >> 9][m0 + (i & 511)];
        __syncthreads();
        for (int mm = lane; mm < 512; mm += 16) {
            float s = 0.f;
#pragma unroll
            for (int r = 0; r < RR; r++) s = fmaf(q[r], ks[r][mm], s);
            sm += __expf(s);
        }
    }
    // reduce over the 16 lanes of this row (stays within half-warp groups)
#pragma unroll
    for (int o = 8; o > 0; o >>= 1)
        sm += __shfl_xor_sync(0xffffffffu, sm, o);
    if (lane == 0) g_invz[d][b][row] = 1.0f / sm;
}

// ---------------------------------------------------------------------------
// K4: out[c,m] = f[c,m] + beta * sum_n V[c,n] * (exp(S[n,m]) * invZ[n])
// The A tile is regenerated in SMEM every K-step (no N x N scratch).
// Block tile: 256(C) x 64(m); K-step 32; thread tile 8x8 (256 threads).
// grid (NN/64, BB, 2).
// ---------------------------------------------------------------------------
#define KT 32
#define MT 64
__global__ __launch_bounds__(256) void k_attn_out(
    const float* __restrict__ fL, const float* __restrict__ fU,
    const float* __restrict__ betap, float* __restrict__ out)
{
    int d = blockIdx.z, b = blockIdx.y;
    int m0 = blockIdx.x * MT;
    int qi = d ? 2 : 0, ki = d ? 3 : 1;

    __shared__ float Ks[RR][MT];    // 2 KB, loaded once per block
    __shared__ float Vs[KT][CC];    // 32 KB, refreshed per K-step
    __shared__ float As[KT][MT];    // 8 KB, regenerated per K-step
    __shared__ float Qs[RR][KT];    // 1 KB
    __shared__ float Zs[KT];

    int tid = threadIdx.x;
    int tx = tid & 7;               // col group: m = m0 + tx*8 + j
    int ty = tid >> 3;              // row group: c = ty*8 + i

    for (int i = tid; i < RR * MT; i += 256)
        Ks[i / MT][i % MT] = g_qk[ki][b][i / MT][m0 + (i % MT)];

    float acc[8][8];
#pragma unroll
    for (int i = 0; i < 8; i++)
#pragma unroll
        for (int j = 0; j < 8; j++) acc[i][j] = 0.f;

    for (int n0 = 0; n0 < NN; n0 += KT) {
        __syncthreads();
        // stage V tile transposed: thread tid owns channel c = tid
        {
            const float4* vp = (const float4*)(&g_v[d][b][tid][n0]);
#pragma unroll
            for (int jj = 0; jj < KT / 4; jj++) {
                float4 v4 = vp[jj];
                Vs[jj * 4 + 0][tid] = v4.x;
                Vs[jj * 4 + 1][tid] = v4.y;
                Vs[jj * 4 + 2][tid] = v4.z;
                Vs[jj * 4 + 3][tid] = v4.w;
            }
        }
        Qs[tid >> 5][tid & 31] = g_qk[qi][b][tid >> 5][n0 + (tid & 31)];
        if (tid < KT) Zs[tid] = g_invz[d][b][n0 + tid];
        __syncthreads();

        // regenerate A tile: 2048 elements / 256 threads = 8 each
#pragma unroll
        for (int e = 0; e < 8; e++) {
            int idx = tid + 256 * e;
            int kk = idx >> 6, mm = idx & 63;
            float s = 0.f;
#pragma unroll
            for (int r = 0; r < RR; r++) s = fmaf(Qs[r][kk], Ks[r][mm], s);
            As[kk][mm] = __expf(s) * Zs[kk];
        }
        __syncthreads();

        // main rank-1 update loop: 64 FMA per kk per thread
#pragma unroll
        for (int kk = 0; kk < KT; kk++) {
            float av[8], vv[8];
#pragma unroll
            for (int j = 0; j < 8; j++) av[j] = As[kk][tx * 8 + j];
#pragma unroll
            for (int i = 0; i < 8; i++) vv[i] = Vs[kk][ty * 8 + i];
#pragma unroll
            for (int i = 0; i < 8; i++)
#pragma unroll
                for (int j = 0; j < 8; j++)
                    acc[i][j] = fmaf(vv[i], av[j], acc[i][j]);
        }
    }

    // epilogue: out = f + beta * acc   (d=0 -> fL2, d=1 -> fU2)
    float beta = *betap;
    const float* f = d ? fU : fL;
    float* op = out + (((size_t)(d * BB + b)) * CC) * NN;
#pragma unroll
    for (int i = 0; i < 8; i++) {
        int c = ty * 8 + i;
        const float4* fp =
            (const float4*)(f + (size_t)b * CC * NN + (size_t)c * NN + m0 + tx * 8);
        float4* opv = (float4*)(op + (size_t)c * NN + m0 + tx * 8);
#pragma unroll
        for (int j4 = 0; j4 < 2; j4++) {
            float4 fv = fp[j4];
            float4 ov;
            ov.x = fv.x + beta * acc[i][j4 * 4 + 0];
            ov.y = fv.y + beta * acc[i][j4 * 4 + 1];
            ov.z = fv.z + beta * acc[i][j4 * 4 + 2];
            ov.w = fv.w + beta * acc[i][j4 * 4 + 3];
            opv[j4] = ov;
        }
    }
}

// ---------------------------------------------------------------------------
// Launch: 4 dependent kernels on the default stream (graph-capturable).
// ---------------------------------------------------------------------------
extern "C" void kernel_launch(void* const* d_in, const int* in_sizes, int n_in,
                              void* d_out, int out_size)
{
    (void)in_sizes; (void)n_in; (void)out_size;
    const float* fL  = (const float*)d_in[0];
    const float* fU  = (const float*)d_in[1];
    const float* qLw = (const float*)d_in[2];
    const float* qLb = (const float*)d_in[3];
    const float* kUw = (const float*)d_in[4];
    const float* kUb = (const float*)d_in[5];
    const float* vUw = (const float*)d_in[6];
    const float* vUb = (const float*)d_in[7];
    const float* qUw = (const float*)d_in[8];
    const float* qUb = (const float*)d_in[9];
    const float* kLw = (const float*)d_in[10];
    const float* kLb = (const float*)d_in[11];
    const float* vLw = (const float*)d_in[12];
    const float* vLb = (const float*)d_in[13];
    const float* beta = (const float*)d_in[14];
    float* out = (float*)d_out;

    k_proj<<<dim3(NN / 256, BB), 256>>>(fL, fU, qLw, qLb, kUw, kUb,
                                        qUw, qUb, kLw, kLb);
    k_vconv<<<dim3(NN / 128, GG, 2 * BB), 128>>>(fL, fU, vUw, vUb, vLw, vLb);
    k_softstats<<<dim3(NN / 16, BB, 2), 256>>>();
    k_attn_out<<<dim3(NN / MT, BB, 2), 256>>>(fL, fU, beta, out);
}

// round 5
// speedup vs baseline: 1.9820x; 1.9820x over previous
#include <cuda_runtime.h>
#include <cuda_bf16.h>
#include <math.h>
#include <stdint.h>

// Problem constants
#define BB 2
#define CC 256
#define NN 4096
#define RR 8
#define GG 4
#define CG 64   // C / G

// Scratch (static device globals: allocation-free rule)
// g_qkT[p][b][n][r]:  p: 0=qL, 1=kU, 2=qU, 3=kL   (transposed: r contiguous)
// g_v[d][b][c][n]:    d=0 -> vU(fU) used by LU, d=1 -> vL(fL) used by UL
// g_invz[d][b][n]:    1 / sum_m exp(S[n,m])
__device__ float g_qkT[4][BB][NN][RR];
__device__ float g_v[2][BB][CC][NN];
__device__ float g_invz[2][BB][NN];

// ---------------------------------------------------------------------------
// helpers
// ---------------------------------------------------------------------------
__device__ __forceinline__ float tf32r(float x) {
    uint32_t u;
    asm("cvt.rna.tf32.f32 %0, %1;" : "=r"(u) : "f"(x));
    return __uint_as_float(u);
}

__device__ __forceinline__ void mma_tf32(float* c, uint32_t a0, uint32_t a1,
                                         uint32_t a2, uint32_t a3,
                                         uint32_t b0, uint32_t b1) {
    asm volatile(
        "mma.sync.aligned.m16n8k8.row.col.f32.tf32.tf32.f32 "
        "{%0,%1,%2,%3}, {%4,%5,%6,%7}, {%8,%9}, {%0,%1,%2,%3};\n"
        : "+f"(c[0]), "+f"(c[1]), "+f"(c[2]), "+f"(c[3])
        : "r"(a0), "r"(a1), "r"(a2), "r"(a3), "r"(b0), "r"(b1));
}

// ---------------------------------------------------------------------------
// K1: fused rank-8 projections; writes transposed layout qkT[n][r].
// grid (NN/256, BB), block 256.
// ---------------------------------------------------------------------------
__global__ __launch_bounds__(256) void k_proj(
    const float* __restrict__ fL, const float* __restrict__ fU,
    const float* __restrict__ qLw, const float* __restrict__ qLb,
    const float* __restrict__ kUw, const float* __restrict__ kUb,
    const float* __restrict__ qUw, const float* __restrict__ qUb,
    const float* __restrict__ kLw, const float* __restrict__ kLb)
{
    __shared__ float ws[4][RR * CC];     // 32 KB of weights
    int tid = threadIdx.x;
    for (int i = tid; i < RR * CC; i += 256) {
        ws[0][i] = qLw[i];
        ws[1][i] = kUw[i];
        ws[2][i] = qUw[i];
        ws[3][i] = kLw[i];
    }
    __syncthreads();

    int b = blockIdx.y;
    int n = blockIdx.x * 256 + tid;
    const float* xl = fL + (size_t)b * CC * NN + n;
    const float* xu = fU + (size_t)b * CC * NN + n;

    float a0[RR], a1[RR], a2[RR], a3[RR];
#pragma unroll
    for (int r = 0; r < RR; r++) { a0[r] = a1[r] = a2[r] = a3[r] = 0.f; }

    for (int c = 0; c < CC; c++) {
        float lx = xl[(size_t)c * NN];
        float ux = xu[(size_t)c * NN];
#pragma unroll
        for (int r = 0; r < RR; r++) {
            a0[r] = fmaf(ws[0][r * CC + c], lx, a0[r]);
            a1[r] = fmaf(ws[1][r * CC + c], ux, a1[r]);
            a2[r] = fmaf(ws[2][r * CC + c], ux, a2[r]);
            a3[r] = fmaf(ws[3][r * CC + c], lx, a3[r]);
        }
    }
    float* t0 = &g_qkT[0][b][n][0];
    float* t1 = &g_qkT[1][b][n][0];
    float* t2 = &g_qkT[2][b][n][0];
    float* t3 = &g_qkT[3][b][n][0];
#pragma unroll
    for (int r = 0; r < RR; r++) {
        t0[r] = a0[r] + qLb[r];
        t1[r] = a1[r] + kUb[r];
        t2[r] = a2[r] + qUb[r];
        t3[r] = a3[r] + kLb[r];
    }
}

// ---------------------------------------------------------------------------
// K2: grouped 1x1x1 v-conv for both directions.
// grid (NN/128, GG, 2*BB), block 128.
// ---------------------------------------------------------------------------
__global__ __launch_bounds__(128) void k_vconv(
    const float* __restrict__ fL, const float* __restrict__ fU,
    const float* __restrict__ vUw, const float* __restrict__ vUb,
    const float* __restrict__ vLw, const float* __restrict__ vLb)
{
    int z = blockIdx.z;
    int d = z >> 1;
    int b = z & 1;
    int g = blockIdx.y;
    int tid = threadIdx.x;
    int n = blockIdx.x * 128 + tid;

    const float* x    = (d == 0) ? fU  : fL;
    const float* wsrc = (d == 0) ? vUw : vLw;
    const float* bsrc = (d == 0) ? vUb : vLb;

    __shared__ float wT[CG][CG];   // wT[ci][co] = w[g][co][ci]
    for (int i = tid; i < CG * CG; i += 128) {
        int co = i / CG, ci = i % CG;
        wT[ci][co] = wsrc[(g * CG + co) * CG + ci];
    }
    __syncthreads();

    float acc[CG];
#pragma unroll
    for (int co = 0; co < CG; co++) acc[co] = 0.f;

    const float* xp = x + ((size_t)b * CC + g * CG) * NN + n;
    for (int ci = 0; ci < CG; ci++) {
        float xv = xp[(size_t)ci * NN];
#pragma unroll
        for (int co = 0; co < CG; co++)
            acc[co] = fmaf(wT[ci][co], xv, acc[co]);
    }
#pragma unroll
    for (int co = 0; co < CG; co++)
        g_v[d][b][g * CG + co][n] = acc[co] + bsrc[g * CG + co];
}

// ---------------------------------------------------------------------------
// K3: softmax normalizers, no max-shift (logits bounded).
// qkT layout gives coalesced float4 k loads straight from L2 (no SMEM).
// grid (NN/16, BB, 2), block 256: 16 rows/block, 16 lanes per row.
// ---------------------------------------------------------------------------
__global__ __launch_bounds__(256) void k_softstats()
{
    int d = blockIdx.z, b = blockIdx.y;
    int tid = threadIdx.x;
    int row  = blockIdx.x * 16 + (tid >> 4);
    int lane = tid & 15;
    int qi = d ? 2 : 0;
    int ki = d ? 3 : 1;

    const float4* qp = (const float4*)&g_qkT[qi][b][row][0];
    float4 qa = qp[0], qb = qp[1];

    const float4* kbase = (const float4*)&g_qkT[ki][b][0][0];

    float sm = 0.f;
    for (int m = lane; m < NN; m += 16) {
        float4 ka = kbase[2 * m];
        float4 kc = kbase[2 * m + 1];
        float s = qa.x * ka.x;
        s = fmaf(qa.y, ka.y, s);
        s = fmaf(qa.z, ka.z, s);
        s = fmaf(qa.w, ka.w, s);
        s = fmaf(qb.x, kc.x, s);
        s = fmaf(qb.y, kc.y, s);
        s = fmaf(qb.z, kc.z, s);
        s = fmaf(qb.w, kc.w, s);
        sm += __expf(s);
    }
#pragma unroll
    for (int o = 8; o > 0; o >>= 1)
        sm += __shfl_xor_sync(0xffffffffu, sm, o);
    if (lane == 0) g_invz[d][b][row] = 1.0f / sm;
}

// ---------------------------------------------------------------------------
// K4: tensor-core GEMM  out[c,m] = f[c,m] + beta * sum_n V[c,n]*A[n,m]
// A tile regenerated in SMEM per K-step (exp * invZ), tf32 mma.sync.
// Block: 256 thr (8 warps), tile 256(C) x 128(m), KT=32.
// Warp tile 64x64: 4 M-tiles x 8 N-tiles of m16n8k8.
// SMEM fragment-paired float2 layout (k, k+4) with XOR swizzle
// kp' = (kp + (idx>>2)) & 3  -> conflict-free LDS.64 loads AND stores.
// grid (NN/128, BB, 2) = 128 blocks.
// ---------------------------------------------------------------------------
#define KT 32
#define MT 128

// dynamic smem layout (bytes):
//   VP  float2[4][256][4]   32768 @ 0
//   AP  float2[4][128][4]   16384 @ 32768
//   Ks  float [128][8]       4096 @ 49152
//   Qs  float [32][8]        1024 @ 53248
//   Zs  float [32]            128 @ 54272
#define SM4_BYTES 54400

__global__ __launch_bounds__(256) void k_attn_out_tc(
    const float* __restrict__ fL, const float* __restrict__ fU,
    const float* __restrict__ betap, float* __restrict__ out)
{
    extern __shared__ unsigned char smem_raw[];
    float2* VP  = (float2*)(smem_raw);
    float2* AP  = (float2*)(smem_raw + 32768);
    float*  Ksh = (float*) (smem_raw + 49152);
    float*  Qsh = (float*) (smem_raw + 53248);
    float*  Zsh = (float*) (smem_raw + 54272);

    int d = blockIdx.z, b = blockIdx.y;
    int m0 = blockIdx.x * MT;
    int qi = d ? 2 : 0, ki = d ? 3 : 1;

    int tid  = threadIdx.x;
    int warp = tid >> 5, lane = tid & 31;
    int wy = warp >> 1, wx = warp & 1;   // 4 warps along C, 2 along m
    int cw = wy * 64, mw = wx * 64;
    int lr = lane >> 2;                  // 0..7
    int lc = lane & 3;                   // 0..3

    // stage K (for A regen) once: Ks[m][r]
    for (int i = tid; i < MT * RR; i += 256) {
        int m = i >> 3, r = i & 7;
        Ksh[i] = g_qkT[ki][b][m0 + m][r];
        (void)m; (void)r;
    }

    float acc[4][8][4];
#pragma unroll
    for (int mt = 0; mt < 4; mt++)
#pragma unroll
        for (int nt = 0; nt < 8; nt++)
#pragma unroll
            for (int q = 0; q < 4; q++) acc[mt][nt][q] = 0.f;

    for (int n0 = 0; n0 < NN; n0 += KT) {
        __syncthreads();   // prior mma reads of VP/AP done

        // ---- stage V tile into paired+swizzled layout (thread owns c=tid)
        {
            const float4* vp = (const float4*)&g_v[d][b][tid][n0];
            int sw = (tid >> 2) & 3;
#pragma unroll
            for (int g = 0; g < 4; g++) {
                float4 lo = vp[2 * g];
                float4 hi = vp[2 * g + 1];
                float lv[4] = {lo.x, lo.y, lo.z, lo.w};
                float hv[4] = {hi.x, hi.y, hi.z, hi.w};
#pragma unroll
                for (int kp = 0; kp < 4; kp++) {
                    VP[g * 1024 + tid * 4 + ((kp + sw) & 3)] =
                        make_float2(tf32r(lv[kp]), tf32r(hv[kp]));
                }
            }
        }
        // ---- stage Q (32x8) and Z (32)
        {
            // tid = k*8 + r exactly covers 256 elements
            Qsh[tid] = g_qkT[qi][b][n0 + (tid >> 3)][tid & 7];
            if (tid < KT) Zsh[tid] = g_invz[d][b][n0 + tid];
        }
        __syncthreads();

        // ---- regenerate A tile: 2048 float2 pairs / 256 thr = 8 each
#pragma unroll
        for (int e = 0; e < 8; e++) {
            int p  = tid + 256 * e;
            int kp = p & 3;
            int m  = (p >> 2) & 127;
            int g  = p >> 9;
            int k0 = g * 8 + kp;

            const float4* Km = (const float4*)&Ksh[m * 8];
            float4 k0v = Km[0], k1v = Km[1];
            const float4* Qk = (const float4*)&Qsh[k0 * 8];
            float4 qa = Qk[0], qb = Qk[1];
            const float4* Qk4 = (const float4*)&Qsh[(k0 + 4) * 8];
            float4 qc = Qk4[0], qd = Qk4[1];

            float s0 = qa.x * k0v.x;
            s0 = fmaf(qa.y, k0v.y, s0); s0 = fmaf(qa.z, k0v.z, s0);
            s0 = fmaf(qa.w, k0v.w, s0); s0 = fmaf(qb.x, k1v.x, s0);
            s0 = fmaf(qb.y, k1v.y, s0); s0 = fmaf(qb.z, k1v.z, s0);
            s0 = fmaf(qb.w, k1v.w, s0);
            float s1 = qc.x * k0v.x;
            s1 = fmaf(qc.y, k0v.y, s1); s1 = fmaf(qc.z, k0v.z, s1);
            s1 = fmaf(qc.w, k0v.w, s1); s1 = fmaf(qd.x, k1v.x, s1);
            s1 = fmaf(qd.y, k1v.y, s1); s1 = fmaf(qd.z, k1v.z, s1);
            s1 = fmaf(qd.w, k1v.w, s1);

            float e0 = __expf(s0) * Zsh[k0];
            float e1 = __expf(s1) * Zsh[k0 + 4];
            AP[g * 512 + m * 4 + ((kp + (m >> 2)) & 3)] =
                make_float2(tf32r(e0), tf32r(e1));
        }
        __syncthreads();

        // ---- mma phase: 4 k8-groups x (4 M-tiles x 8 N-tiles)
#pragma unroll
        for (int g = 0; g < 4; g++) {
            uint32_t af[4][4];
#pragma unroll
            for (int mt = 0; mt < 4; mt++) {
                int c0 = cw + mt * 16 + lr;
                int c1 = c0 + 8;
                float2 p0 = VP[g * 1024 + c0 * 4 + ((lc + (c0 >> 2)) & 3)];
                float2 p1 = VP[g * 1024 + c1 * 4 + ((lc + (c1 >> 2)) & 3)];
                af[mt][0] = __float_as_uint(p0.x);
                af[mt][1] = __float_as_uint(p1.x);
                af[mt][2] = __float_as_uint(p0.y);
                af[mt][3] = __float_as_uint(p1.y);
            }
#pragma unroll
            for (int nt = 0; nt < 8; nt++) {
                int n = mw + nt * 8 + lr;
                float2 pb = AP[g * 512 + n * 4 + ((lc + (n >> 2)) & 3)];
                uint32_t b0 = __float_as_uint(pb.x);
                uint32_t b1 = __float_as_uint(pb.y);
#pragma unroll
                for (int mt = 0; mt < 4; mt++)
                    mma_tf32(acc[mt][nt], af[mt][0], af[mt][1], af[mt][2],
                             af[mt][3], b0, b1);
            }
        }
    }

    // ---- epilogue: out = f + beta * acc
    float beta = *betap;
    const float* fsrc = (d ? fU : fL) + (size_t)b * CC * NN;
    float* op = out + (size_t)(d * BB + b) * CC * NN;
#pragma unroll
    for (int mt = 0; mt < 4; mt++) {
        int c0 = cw + mt * 16 + lr;
        int c1 = c0 + 8;
#pragma unroll
        for (int nt = 0; nt < 8; nt++) {
            int m = m0 + mw + nt * 8 + 2 * lc;
            float2 f0 = *(const float2*)&fsrc[(size_t)c0 * NN + m];
            float2 f1 = *(const float2*)&fsrc[(size_t)c1 * NN + m];
            float2 o0 = make_float2(f0.x + beta * acc[mt][nt][0],
                                    f0.y + beta * acc[mt][nt][1]);
            float2 o1 = make_float2(f1.x + beta * acc[mt][nt][2],
                                    f1.y + beta * acc[mt][nt][3]);
            *(float2*)&op[(size_t)c0 * NN + m] = o0;
            *(float2*)&op[(size_t)c1 * NN + m] = o1;
        }
    }
}

// ---------------------------------------------------------------------------
// Launch: 4 dependent kernels on the default stream (graph-capturable).
// ---------------------------------------------------------------------------
extern "C" void kernel_launch(void* const* d_in, const int* in_sizes, int n_in,
                              void* d_out, int out_size)
{
    (void)in_sizes; (void)n_in; (void)out_size;
    const float* fL  = (const float*)d_in[0];
    const float* fU  = (const float*)d_in[1];
    const float* qLw = (const float*)d_in[2];
    const float* qLb = (const float*)d_in[3];
    const float* kUw = (const float*)d_in[4];
    const float* kUb = (const float*)d_in[5];
    const float* vUw = (const float*)d_in[6];
    const float* vUb = (const float*)d_in[7];
    const float* qUw = (const float*)d_in[8];
    const float* qUb = (const float*)d_in[9];
    const float* kLw = (const float*)d_in[10];
    const float* kLb = (const float*)d_in[11];
    const float* vLw = (const float*)d_in[12];
    const float* vLb = (const float*)d_in[13];
    const float* beta = (const float*)d_in[14];
    float* out = (float*)d_out;

    static bool attr_set = false;
    if (!attr_set) {
        cudaFuncSetAttribute(k_attn_out_tc,
                             cudaFuncAttributeMaxDynamicSharedMemorySize,
                             SM4_BYTES);
        attr_set = true;
    }

    k_proj<<<dim3(NN / 256, BB), 256>>>(fL, fU, qLw, qLb, kUw, kUb,
                                        qUw, qUb, kLw, kLb);
    k_vconv<<<dim3(NN / 128, GG, 2 * BB), 128>>>(fL, fU, vUw, vUb, vLw, vLb);
    k_softstats<<<dim3(NN / 16, BB, 2), 256>>>();
    k_attn_out_tc<<<dim3(NN / MT, BB, 2), 256, SM4_BYTES>>>(fL, fU, beta, out);
}

// round 6
// speedup vs baseline: 2.6577x; 1.3409x over previous
#include <cuda_runtime.h>
#include <cuda_bf16.h>
#include <math.h>
#include <stdint.h>

// Problem constants
#define BB 2
#define CC 256
#define NN 4096
#define RR 8
#define GG 4
#define CG 64   // C / G

// Scratch (static device globals: allocation-free rule)
// g_qkT[p][b][n][r]:  p: 0=qL, 1=kU, 2=qU, 3=kL   (transposed: r contiguous)
// g_v[d][b][c][n]:    d=0 -> vU(fU) used by LU, d=1 -> vL(fL) used by UL
// g_lz[d][b][n]:      -log( sum_m exp(S[n,m]) )
__device__ float g_qkT[4][BB][NN][RR];
__device__ float g_v[2][BB][CC][NN];
__device__ float g_lz[2][BB][NN];

// ---------------------------------------------------------------------------
// helpers
// ---------------------------------------------------------------------------
__device__ __forceinline__ uint32_t bf2(float lo, float hi) {
    // d<31:16> = cvt(a)=hi, d<15:0> = cvt(b)=lo
    uint32_t r;
    asm("cvt.rn.bf16x2.f32 %0, %1, %2;" : "=r"(r) : "f"(hi), "f"(lo));
    return r;
}

__device__ __forceinline__ void mma_bf16(float* c, uint32_t a0, uint32_t a1,
                                         uint32_t a2, uint32_t a3,
                                         uint32_t b0, uint32_t b1) {
    asm volatile(
        "mma.sync.aligned.m16n8k16.row.col.f32.bf16.bf16.f32 "
        "{%0,%1,%2,%3}, {%4,%5,%6,%7}, {%8,%9}, {%0,%1,%2,%3};\n"
        : "+f"(c[0]), "+f"(c[1]), "+f"(c[2]), "+f"(c[3])
        : "r"(a0), "r"(a1), "r"(a2), "r"(a3), "r"(b0), "r"(b1));
}

__device__ __forceinline__ float dot8(float4 qa, float4 qb, float4 ka, float4 kb) {
    float s = qa.x * ka.x;
    s = fmaf(qa.y, ka.y, s); s = fmaf(qa.z, ka.z, s); s = fmaf(qa.w, ka.w, s);
    s = fmaf(qb.x, kb.x, s); s = fmaf(qb.y, kb.y, s);
    s = fmaf(qb.z, kb.z, s); s = fmaf(qb.w, kb.w, s);
    return s;
}

// ---------------------------------------------------------------------------
// K1: fused rank-8 projections, 4-way C-split per block for parallelism.
// grid (NN/64, BB) = 128 blocks, block 256: tid = cs*64 + nn.
// Each thread accumulates 32 partials (4 proj x 8 r) over 64 channels;
// the weight SMEM is reused post-loop as the reduction buffer.
// ---------------------------------------------------------------------------
__global__ __launch_bounds__(256) void k_proj(
    const float* __restrict__ fL, const float* __restrict__ fU,
    const float* __restrict__ qLw, const float* __restrict__ qLb,
    const float* __restrict__ kUw, const float* __restrict__ kUb,
    const float* __restrict__ qUw, const float* __restrict__ qUb,
    const float* __restrict__ kLw, const float* __restrict__ kLb)
{
    __shared__ float ws[4][RR * CC];     // 32 KB; reused as reduction buffer
    int tid = threadIdx.x;
    for (int i = tid; i < RR * CC; i += 256) {
        ws[0][i] = qLw[i];
        ws[1][i] = kUw[i];
        ws[2][i] = qUw[i];
        ws[3][i] = kLw[i];
    }
    __syncthreads();

    int b  = blockIdx.y;
    int nn = tid & 63;
    int cs = tid >> 6;                    // 0..3 channel split
    int n  = blockIdx.x * 64 + nn;
    const float* xl = fL + (size_t)b * CC * NN + n;
    const float* xu = fU + (size_t)b * CC * NN + n;

    float a0[RR], a1[RR], a2[RR], a3[RR];
#pragma unroll
    for (int r = 0; r < RR; r++) { a0[r] = a1[r] = a2[r] = a3[r] = 0.f; }

    int cbase = cs * 64;
    for (int cc = 0; cc < 64; cc++) {
        int c = cbase + cc;
        float lx = xl[(size_t)c * NN];
        float ux = xu[(size_t)c * NN];
#pragma unroll
        for (int r = 0; r < RR; r++) {
            a0[r] = fmaf(ws[0][r * CC + c], lx, a0[r]);
            a1[r] = fmaf(ws[1][r * CC + c], ux, a1[r]);
            a2[r] = fmaf(ws[2][r * CC + c], ux, a2[r]);
            a3[r] = fmaf(ws[3][r * CC + c], lx, a3[r]);
        }
    }
    __syncthreads();                      // done reading weights
    float* red = &ws[0][0];               // [3][64][33] padded
    if (cs > 0) {
        float* rp = red + (size_t)(cs - 1) * 64 * 33 + nn * 33;
#pragma unroll
        for (int r = 0; r < RR; r++) {
            rp[r]      = a0[r];
            rp[8 + r]  = a1[r];
            rp[16 + r] = a2[r];
            rp[24 + r] = a3[r];
        }
    }
    __syncthreads();
    if (cs == 0) {
#pragma unroll
        for (int t = 0; t < 3; t++) {
            float* rp = red + (size_t)t * 64 * 33 + nn * 33;
#pragma unroll
            for (int r = 0; r < RR; r++) {
                a0[r] += rp[r];
                a1[r] += rp[8 + r];
                a2[r] += rp[16 + r];
                a3[r] += rp[24 + r];
            }
        }
        float* t0 = &g_qkT[0][b][n][0];
        float* t1 = &g_qkT[1][b][n][0];
        float* t2 = &g_qkT[2][b][n][0];
        float* t3 = &g_qkT[3][b][n][0];
#pragma unroll
        for (int r = 0; r < RR; r++) {
            t0[r] = a0[r] + qLb[r];
            t1[r] = a1[r] + kUb[r];
            t2[r] = a2[r] + qUb[r];
            t3[r] = a3[r] + kLb[r];
        }
    }
}

// ---------------------------------------------------------------------------
// K2: grouped 1x1x1 v-conv for both directions.
// grid (NN/128, GG, 2*BB), block 128.
// ---------------------------------------------------------------------------
__global__ __launch_bounds__(128) void k_vconv(
    const float* __restrict__ fL, const float* __restrict__ fU,
    const float* __restrict__ vUw, const float* __restrict__ vUb,
    const float* __restrict__ vLw, const float* __restrict__ vLb)
{
    int z = blockIdx.z;
    int d = z >> 1;
    int b = z & 1;
    int g = blockIdx.y;
    int tid = threadIdx.x;
    int n = blockIdx.x * 128 + tid;

    const float* x    = (d == 0) ? fU  : fL;
    const float* wsrc = (d == 0) ? vUw : vLw;
    const float* bsrc = (d == 0) ? vUb : vLb;

    __shared__ float wT[CG][CG];   // wT[ci][co] = w[g][co][ci]
    for (int i = tid; i < CG * CG; i += 128) {
        int co = i / CG, ci = i % CG;
        wT[ci][co] = wsrc[(g * CG + co) * CG + ci];
    }
    __syncthreads();

    float acc[CG];
#pragma unroll
    for (int co = 0; co < CG; co++) acc[co] = 0.f;

    const float* xp = x + ((size_t)b * CC + g * CG) * NN + n;
    for (int ci = 0; ci < CG; ci++) {
        float xv = xp[(size_t)ci * NN];
#pragma unroll
        for (int co = 0; co < CG; co++)
            acc[co] = fmaf(wT[ci][co], xv, acc[co]);
    }
#pragma unroll
    for (int co = 0; co < CG; co++)
        g_v[d][b][g * CG + co][n] = acc[co] + bsrc[g * CG + co];
}

// ---------------------------------------------------------------------------
// K3: softmax log-normalizers (no max-shift; logits bounded):
//   lz[n] = -log( sum_m exp(q[n].k[m]) )
// grid (NN/16, BB, 2), block 256: 16 rows/block, 16 lanes per row.
// ---------------------------------------------------------------------------
__global__ __launch_bounds__(256) void k_softstats()
{
    int d = blockIdx.z, b = blockIdx.y;
    int tid = threadIdx.x;
    int row  = blockIdx.x * 16 + (tid >> 4);
    int lane = tid & 15;
    int qi = d ? 2 : 0;
    int ki = d ? 3 : 1;

    const float4* qp = (const float4*)&g_qkT[qi][b][row][0];
    float4 qa = qp[0], qb = qp[1];
    const float4* kbase = (const float4*)&g_qkT[ki][b][0][0];

    float sm = 0.f;
    for (int m = lane; m < NN; m += 16) {
        float4 ka = kbase[2 * m];
        float4 kc = kbase[2 * m + 1];
        sm += __expf(dot8(qa, qb, ka, kc));
    }
#pragma unroll
    for (int o = 8; o > 0; o >>= 1)
        sm += __shfl_xor_sync(0xffffffffu, sm, o);
    if (lane == 0) g_lz[d][b][row] = -__logf(sm);
}

// ---------------------------------------------------------------------------
// K4: bf16 tensor-core GEMM, out[c,m] = f[c,m] + beta * sum_n V[c,n]*A[n,m]
// A[n,m] = exp(q[n].k[m] + lz[n]) regenerated in SMEM per K-step.
// Software-pipelined with double-buffered SMEM:
//   stage(i+1) | bar | regen_g0(i+1); mma_g0(i); regen_g1(i+1); mma_g1(i) | bar
// Block: 256 thr (8 warps), tile 256(C) x 128(m), KT=32 (2 k16-groups).
// Warp tile 64x64: 4 M-tiles x 8 N-tiles of m16n8k16.
// SMEM uint2 fragment pairs (k-pair p, p+4) with XOR swizzle
//   slot = (p + c + (c>>2)) & 3  -> conflict-free LDS.64 and STS.64.
// grid (NN/128, BB, 2) = 128 blocks.
// ---------------------------------------------------------------------------
#define KT 32
#define MT 128

// dynamic smem (bytes):
//   VB uint2[2 buf][2 g][256 c][4 slot]  32768 @ 0
//   AB uint2[2 buf][2 g][128 n][4 slot]  16384 @ 32768
//   Qb float[2 buf][32][8]                2048 @ 49152
//   Lz float[2 buf][32]                    256 @ 51200
//   Ks float[128][8]                      4096 @ 51456
#define SM4_BYTES 55552

__global__ __launch_bounds__(256) void k_attn_out_tc(
    const float* __restrict__ fL, const float* __restrict__ fU,
    const float* __restrict__ betap, float* __restrict__ out)
{
    extern __shared__ unsigned char sm[];
    uint2* VB  = (uint2*)(sm);               // region stride per (buf,g): 1024
    uint2* AB  = (uint2*)(sm + 32768);       // region stride per (buf,g): 512
    float* Qb  = (float*)(sm + 49152);
    float* Lzb = (float*)(sm + 51200);
    float* Ksh = (float*)(sm + 51456);

    int d = blockIdx.z, b = blockIdx.y;
    int m0 = blockIdx.x * MT;
    int qi = d ? 2 : 0, ki = d ? 3 : 1;

    int tid  = threadIdx.x;
    int warp = tid >> 5, lane = tid & 31;
    int wy = warp >> 1, wx = warp & 1;   // 4 warps along C, 2 along m
    int cw = wy * 64, mw = wx * 64;
    int lr = lane >> 2;                  // 0..7
    int lc = lane & 3;                   // 0..3

    const float* qsrc = &g_qkT[qi][b][0][0];
    const float* lzsrc = &g_lz[d][b][0];
    const float* vsrc = &g_v[d][b][tid][0];

    // K for A-regen, loaded once (contiguous 4KB)
    {
        const float* ksrc = &g_qkT[ki][b][m0][0];
        for (int i = tid; i < MT * RR; i += 256) Ksh[i] = ksrc[i];
    }

    // precomputed swizzled fragment offsets (within a (buf,g) region)
    int aoff[4][2];
#pragma unroll
    for (int mt = 0; mt < 4; mt++) {
        int c0 = cw + mt * 16 + lr;
        int c1 = c0 + 8;
        aoff[mt][0] = c0 * 4 + ((lc + c0 + (c0 >> 2)) & 3);
        aoff[mt][1] = c1 * 4 + ((lc + c1 + (c1 >> 2)) & 3);
    }
    int boff[8];
#pragma unroll
    for (int nt = 0; nt < 8; nt++) {
        int n = mw + nt * 8 + lr;
        boff[nt] = n * 4 + ((lc + n + (n >> 2)) & 3);
    }
    int vsw = (tid + (tid >> 2)) & 3;    // staging swizzle base for c = tid
    int rp  = tid & 3;                   // regen pair id
    int rnb = tid >> 2;                  // regen n base (0..63)

    float acc[4][8][4];
#pragma unroll
    for (int mt = 0; mt < 4; mt++)
#pragma unroll
        for (int nt = 0; nt < 8; nt++)
#pragma unroll
            for (int q = 0; q < 4; q++) acc[mt][nt][q] = 0.f;

#define STAGE(J) do {                                                          \
    int jj = (J); int bu = jj & 1; int n0 = jj * KT;                           \
    const float4* vp = (const float4*)(vsrc + n0);                             \
    _Pragma("unroll")                                                          \
    for (int g = 0; g < 2; g++) {                                              \
        float4 va = vp[4 * g + 0], vb = vp[4 * g + 1];                         \
        float4 vc = vp[4 * g + 2], vd = vp[4 * g + 3];                         \
        uint2* dst = VB + (bu * 2 + g) * 1024 + tid * 4;                       \
        dst[(0 + vsw) & 3] = make_uint2(bf2(va.x, va.y), bf2(vc.x, vc.y));     \
        dst[(1 + vsw) & 3] = make_uint2(bf2(va.z, va.w), bf2(vc.z, vc.w));     \
        dst[(2 + vsw) & 3] = make_uint2(bf2(vb.x, vb.y), bf2(vd.x, vd.y));     \
        dst[(3 + vsw) & 3] = make_uint2(bf2(vb.z, vb.w), bf2(vd.z, vd.w));     \
    }                                                                          \
    Qb[bu * 256 + tid] = qsrc[n0 * 8 + tid];                                   \
    if (tid < KT) Lzb[bu * 32 + tid] = lzsrc[n0 + tid];                        \
} while (0)

#define REGEN_G(J, G) do {                                                     \
    int jj = (J); int bu = jj & 1;                                             \
    const float* qb = Qb + bu * 256;                                           \
    const float* lzp = Lzb + bu * 32;                                          \
    int k0 = (G) * 16 + 2 * rp;                                                \
    float4 q0a = *(const float4*)&qb[k0 * 8];                                  \
    float4 q0b = *(const float4*)&qb[k0 * 8 + 4];                              \
    float4 q1a = *(const float4*)&qb[(k0 + 1) * 8];                            \
    float4 q1b = *(const float4*)&qb[(k0 + 1) * 8 + 4];                        \
    float4 q2a = *(const float4*)&qb[(k0 + 8) * 8];                            \
    float4 q2b = *(const float4*)&qb[(k0 + 8) * 8 + 4];                        \
    float4 q3a = *(const float4*)&qb[(k0 + 9) * 8];                            \
    float4 q3b = *(const float4*)&qb[(k0 + 9) * 8 + 4];                        \
    float z0 = lzp[k0], z1 = lzp[k0 + 1], z2 = lzp[k0 + 8], z3 = lzp[k0 + 9];  \
    _Pragma("unroll")                                                          \
    for (int e2 = 0; e2 < 2; e2++) {                                           \
        int m = (rnb + 64 * ((G) * 2 + e2)) & 127;                             \
        float4 ka = *(const float4*)&Ksh[m * 8];                               \
        float4 kb = *(const float4*)&Ksh[m * 8 + 4];                           \
        float e0 = __expf(dot8(q0a, q0b, ka, kb) + z0);                        \
        float e1 = __expf(dot8(q1a, q1b, ka, kb) + z1);                        \
        float e2v = __expf(dot8(q2a, q2b, ka, kb) + z2);                       \
        float e3 = __expf(dot8(q3a, q3b, ka, kb) + z3);                        \
        AB[(bu * 2 + (G)) * 512 + m * 4 + ((rp + m + (m >> 2)) & 3)] =         \
            make_uint2(bf2(e0, e1), bf2(e2v, e3));                             \
    }                                                                          \
} while (0)

#define MMA_G(J, G) do {                                                       \
    int bu = (J) & 1;                                                          \
    const uint2* vr = VB + (bu * 2 + (G)) * 1024;                              \
    const uint2* ar = AB + (bu * 2 + (G)) * 512;                               \
    uint2 av[4][2];                                                            \
    _Pragma("unroll")                                                          \
    for (int mt = 0; mt < 4; mt++) {                                           \
        av[mt][0] = vr[aoff[mt][0]];                                           \
        av[mt][1] = vr[aoff[mt][1]];                                           \
    }                                                                          \
    _Pragma("unroll")                                                          \
    for (int nt = 0; nt < 8; nt++) {                                           \
        uint2 bb = ar[boff[nt]];                                               \
        _Pragma("unroll")                                                      \
        for (int mt = 0; mt < 4; mt++)                                         \
            mma_bf16(acc[mt][nt], av[mt][0].x, av[mt][1].x,                    \
                     av[mt][0].y, av[mt][1].y, bb.x, bb.y);                    \
    }                                                                          \
} while (0)

    // pipeline prologue
    STAGE(0);
    __syncthreads();
    REGEN_G(0, 0);
    REGEN_G(0, 1);
    __syncthreads();

    for (int j = 0; j < NN / KT; j++) {
        if (j + 1 < NN / KT) STAGE(j + 1);
        __syncthreads();
        if (j + 1 < NN / KT) {
            REGEN_G(j + 1, 0);
            MMA_G(j, 0);
            REGEN_G(j + 1, 1);
            MMA_G(j, 1);
        } else {
            MMA_G(j, 0);
            MMA_G(j, 1);
        }
        __syncthreads();
    }

    // epilogue: out = f + beta * acc
    float beta = *betap;
    const float* fsrc = (d ? fU : fL) + (size_t)b * CC * NN;
    float* op = out + (size_t)(d * BB + b) * CC * NN;
#pragma unroll
    for (int mt = 0; mt < 4; mt++) {
        int c0 = cw + mt * 16 + lr;
        int c1 = c0 + 8;
#pragma unroll
        for (int nt = 0; nt < 8; nt++) {
            int m = m0 + mw + nt * 8 + 2 * lc;
            float2 f0 = *(const float2*)&fsrc[(size_t)c0 * NN + m];
            float2 f1 = *(const float2*)&fsrc[(size_t)c1 * NN + m];
            float2 o0 = make_float2(f0.x + beta * acc[mt][nt][0],
                                    f0.y + beta * acc[mt][nt][1]);
            float2 o1 = make_float2(f1.x + beta * acc[mt][nt][2],
                                    f1.y + beta * acc[mt][nt][3]);
            *(float2*)&op[(size_t)c0 * NN + m] = o0;
            *(float2*)&op[(size_t)c1 * NN + m] = o1;
        }
    }
}

// ---------------------------------------------------------------------------
// Launch: 4 dependent kernels on the default stream (graph-capturable).
// ---------------------------------------------------------------------------
extern "C" void kernel_launch(void* const* d_in, const int* in_sizes, int n_in,
                              void* d_out, int out_size)
{
    (void)in_sizes; (void)n_in; (void)out_size;
    const float* fL  = (const float*)d_in[0];
    const float* fU  = (const float*)d_in[1];
    const float* qLw = (const float*)d_in[2];
    const float* qLb = (const float*)d_in[3];
    const float* kUw = (const float*)d_in[4];
    const float* kUb = (const float*)d_in[5];
    const float* vUw = (const float*)d_in[6];
    const float* vUb = (const float*)d_in[7];
    const float* qUw = (const float*)d_in[8];
    const float* qUb = (const float*)d_in[9];
    const float* kLw = (const float*)d_in[10];
    const float* kLb = (const float*)d_in[11];
    const float* vLw = (const float*)d_in[12];
    const float* vLb = (const float*)d_in[13];
    const float* beta = (const float*)d_in[14];
    float* out = (float*)d_out;

    static bool attr_set = false;
    if (!attr_set) {
        cudaFuncSetAttribute(k_attn_out_tc,
                             cudaFuncAttributeMaxDynamicSharedMemorySize,
                             SM4_BYTES);
        attr_set = true;
    }

    k_proj<<<dim3(NN / 64, BB), 256>>>(fL, fU, qLw, qLb, kUw, kUb,
                                       qUw, qUb, kLw, kLb);
    k_vconv<<<dim3(NN / 128, GG, 2 * BB), 128>>>(fL, fU, vUw, vUb, vLw, vLb);
    k_softstats<<<dim3(NN / 16, BB, 2), 256>>>();
    k_attn_out_tc<<<dim3(NN / MT, BB, 2), 256, SM4_BYTES>>>(fL, fU, beta, out);
}